// round 1
// baseline (speedup 1.0000x reference)
#include <cuda_runtime.h>
#include <math.h>

#define SS   512
#define BB   64
#define HH   512
#define EE   512
#define MD   1024
#define NC   20
#define BH   (BB*HH)     // 32768
#define NROW (SS*BB)     // 32768
#define NSC  32          // s-chunks in phase C

// ---------------- scratch (static device memory; no allocs) ----------------
__device__ float g_emb[(size_t)NROW*EE];   // gathered embeddings   [s][b][e]
__device__ float g_els[(size_t)NROW*HH];   // emb @ W_sl^T + b_sl   [s][b][h]
__device__ float g_ers[(size_t)NROW*HH];   // emb @ W_sr^T + b_sr   [s][b][h]
__device__ float g_cl [(size_t)NROW*HH];   // forward scan history  [s][b][h]
__device__ float g_cr [(size_t)NROW*HH];   // backward scan history [s][b][h]
__device__ float g_ctl[HH*BB];             // current fwd c, transposed [h][b]
__device__ float g_ctr[HH*BB];             // current bwd c, transposed [h][b]
__device__ float g_part[(size_t)NSC*BB*MD];// partial max of z      [sc][b][m]

__device__ unsigned g_bar_count;
__device__ volatile unsigned g_bar_gen;

// ---------------- software grid barrier (all CTAs wave-1 resident) ---------
__device__ __forceinline__ void grid_barrier() {
    __threadfence();                 // release: make this thread's writes visible
    __syncthreads();
    if (threadIdx.x == 0) {
        unsigned gen = g_bar_gen;
        if (atomicAdd(&g_bar_count, 1u) == gridDim.x - 1) {
            g_bar_count = 0;
            __threadfence();
            g_bar_gen = gen + 1;
        } else {
            while (g_bar_gen == gen) { }
        }
    }
    __syncthreads();
    __threadfence();                 // acquire side
}

// ---------------- K0: embedding gather -------------------------------------
__global__ void gather_kernel(const int* __restrict__ inp,
                              const float* __restrict__ table) {
    int sb = blockIdx.x;                       // 0..32767
    int tok = inp[sb];
    const float4* src = reinterpret_cast<const float4*>(table + (size_t)tok * EE);
    float4* dst = reinterpret_cast<float4*>(g_emb + (size_t)sb * EE);
    dst[threadIdx.x] = src[threadIdx.x];       // 128 threads x float4 = 512 f
}

// ---------------- K0b: init transposed c state ------------------------------
__global__ void init_ct_kernel(const float* __restrict__ cl0,
                               const float* __restrict__ cr0) {
    int idx = blockIdx.x * blockDim.x + threadIdx.x;   // idx = k*64 + b
    if (idx < HH * BB) {
        int k = idx >> 6;
        g_ctl[idx] = cl0[k];
        g_ctr[idx] = cr0[k];
    }
}

// ---------------- K1: dual projection GEMM (emb_ls, emb_rs) -----------------
// rows = 32768 (s,b), cols = 512 (h), K = 512 (e). CTA tile 64x64, thread 4x4.
__global__ void proj_kernel(const float* __restrict__ Wsl, const float* __restrict__ bsl,
                            const float* __restrict__ Wsr, const float* __restrict__ bsr) {
    __shared__ float Ash[32][68];
    __shared__ float Bls[32][68];
    __shared__ float Brs[32][68];
    const int row0 = blockIdx.x * 64;
    const int col0 = blockIdx.y * 64;
    const int t  = threadIdx.x;
    const int tr = (t >> 4) * 4;
    const int tc = (t & 15) * 4;
    float accL[4][4]; float accR[4][4];
    #pragma unroll
    for (int r = 0; r < 4; ++r)
        #pragma unroll
        for (int c = 0; c < 4; ++c) { accL[r][c] = 0.f; accR[r][c] = 0.f; }

    for (int kc = 0; kc < EE; kc += 32) {
        for (int i = t; i < 2048; i += 256) {
            int r  = i >> 5;
            int kk = i & 31;
            Ash[kk][r] = g_emb[(size_t)(row0 + r) * EE + kc + kk];
            Bls[kk][r] = Wsl[(size_t)(col0 + r) * EE + kc + kk];
            Brs[kk][r] = Wsr[(size_t)(col0 + r) * EE + kc + kk];
        }
        __syncthreads();
        #pragma unroll
        for (int kk = 0; kk < 32; ++kk) {
            float4 a  = *reinterpret_cast<const float4*>(&Ash[kk][tr]);
            float4 bL = *reinterpret_cast<const float4*>(&Bls[kk][tc]);
            float4 bR = *reinterpret_cast<const float4*>(&Brs[kk][tc]);
            float av[4]  = {a.x, a.y, a.z, a.w};
            float bLv[4] = {bL.x, bL.y, bL.z, bL.w};
            float bRv[4] = {bR.x, bR.y, bR.z, bR.w};
            #pragma unroll
            for (int r = 0; r < 4; ++r)
                #pragma unroll
                for (int c = 0; c < 4; ++c) {
                    accL[r][c] += av[r] * bLv[c];
                    accR[r][c] += av[r] * bRv[c];
                }
        }
        __syncthreads();
    }
    #pragma unroll
    for (int r = 0; r < 4; ++r) {
        int row = row0 + tr + r;
        #pragma unroll
        for (int c = 0; c < 4; ++c) {
            int col = col0 + tc + c;
            g_els[(size_t)row * HH + col] = accL[r][c] + bsl[col];
            g_ers[(size_t)row * HH + col] = accR[r][c] + bsr[col];
        }
    }
}

// ---------------- K2: persistent bidirectional scan -------------------------
// 128 CTAs: 0..63 forward, 64..127 backward. Each CTA owns 8 output columns;
// threads split K into 4 groups (64 threads each), 4 batches x 2 cols each.
__global__ void scan_kernel(const float* __restrict__ Wl, const float* __restrict__ bl,
                            const float* __restrict__ Wr, const float* __restrict__ br) {
    __shared__ float Wsh[HH][8];       // 16 KB: this CTA's 8 rows of W (as W[j][k] -> Wsh[k][jl])
    __shared__ float part[4][520];     // k-split partials, padded vs bank conflicts

    const int dir = (blockIdx.x >= 64);
    const int cb  = (blockIdx.x & 63) * 8;
    const float* W    = dir ? Wr    : Wl;
    const float* bias = dir ? br    : bl;
    const float* e    = dir ? g_ers : g_els;
    float* ct   = dir ? g_ctr : g_ctl;
    float* hist = dir ? g_cr  : g_cl;

    const int t = threadIdx.x;
    for (int i = t; i < 8 * HH; i += 256) {
        int jl = i >> 9;
        int k  = i & 511;
        Wsh[k][jl] = W[(size_t)(cb + jl) * HH + k];
    }
    const int kg    = t >> 6;          // k-split group 0..3
    const int t6    = t & 63;
    const int jl0   = (t6 & 3) * 2;    // local col pair
    const int bg    = t6 >> 2;         // batch quad 0..15
    const int kbase = kg * 128;
    const float4* cv = reinterpret_cast<const float4*>(ct);
    __syncthreads();

    for (int step = 0; step < SS; ++step) {
        const int s = dir ? (SS - 1 - step) : step;
        float a00=0.f,a01=0.f,a10=0.f,a11=0.f,a20=0.f,a21=0.f,a30=0.f,a31=0.f;
        #pragma unroll 8
        for (int k = 0; k < 128; ++k) {
            int kk = kbase + k;
            float4 c4 = __ldcg(&cv[kk * 16 + bg]);              // ct[kk][4*bg..+3]
            float2 w2 = *reinterpret_cast<const float2*>(&Wsh[kk][jl0]);
            a00 += c4.x * w2.x;  a01 += c4.x * w2.y;
            a10 += c4.y * w2.x;  a11 += c4.y * w2.y;
            a20 += c4.z * w2.x;  a21 += c4.z * w2.y;
            a30 += c4.w * w2.x;  a31 += c4.w * w2.y;
        }
        const int ob0 = bg * 4;
        part[kg][(jl0+0)*65 + ob0+0] = a00;  part[kg][(jl0+1)*65 + ob0+0] = a01;
        part[kg][(jl0+0)*65 + ob0+1] = a10;  part[kg][(jl0+1)*65 + ob0+1] = a11;
        part[kg][(jl0+0)*65 + ob0+2] = a20;  part[kg][(jl0+1)*65 + ob0+2] = a21;
        part[kg][(jl0+0)*65 + ob0+3] = a30;  part[kg][(jl0+1)*65 + ob0+3] = a31;
        __syncthreads();

        for (int o = t; o < 512; o += 256) {
            int ob = o >> 3, oj = o & 7;
            int pi = oj * 65 + ob;
            float v = part[0][pi] + part[1][pi] + part[2][pi] + part[3][pi];
            v += bias[cb + oj] + e[(size_t)s * BH + (size_t)ob * HH + cb + oj];
            v = tanhf(v);
            hist[(size_t)s * BH + (size_t)ob * HH + cb + oj] = v;
            ct[(size_t)(cb + oj) * BB + ob] = v;                // transposed for next step
        }
        grid_barrier();
    }
}

// ---------------- K3: z = cat @ Wmax^T, running max over s ------------------
// tanh is monotonic -> max_s tanh(z+b) = tanh(max_s z + b): skip per-element tanh.
__global__ void ymax_kernel(const float* __restrict__ Wmax) {
    __shared__ float Ash[32][68];
    __shared__ float Bsh[32][68];
    const int m0 = blockIdx.x * 64;    // 16 m-tiles
    const int sc = blockIdx.y;         // 32 s-chunks of 16
    const int t  = threadIdx.x;
    const int tb = (t >> 4) * 4;
    const int tm = (t & 15) * 4;
    float zmax[4][4];
    #pragma unroll
    for (int r = 0; r < 4; ++r)
        #pragma unroll
        for (int c = 0; c < 4; ++c) zmax[r][c] = -3.402823466e38f;

    for (int s = sc * 16; s < sc * 16 + 16; ++s) {
        float acc[4][4];
        #pragma unroll
        for (int r = 0; r < 4; ++r)
            #pragma unroll
            for (int c = 0; c < 4; ++c) acc[r][c] = 0.f;

        for (int kc = 0; kc < 1536; kc += 32) {
            const float* Asrc;
            if (kc < 512)        Asrc = g_cl  + (size_t)s * BH + kc;
            else if (kc < 1024)  Asrc = g_emb + (size_t)s * BH + (kc - 512);
            else                 Asrc = g_cr  + (size_t)s * BH + (kc - 1024);
            for (int i = t; i < 2048; i += 256) {
                int r  = i >> 5;
                int kk = i & 31;
                Ash[kk][r] = Asrc[(size_t)r * 512 + kk];
                Bsh[kk][r] = Wmax[(size_t)(m0 + r) * 1536 + kc + kk];
            }
            __syncthreads();
            #pragma unroll
            for (int kk = 0; kk < 32; ++kk) {
                float4 a = *reinterpret_cast<const float4*>(&Ash[kk][tb]);
                float4 b = *reinterpret_cast<const float4*>(&Bsh[kk][tm]);
                float av[4] = {a.x, a.y, a.z, a.w};
                float bv[4] = {b.x, b.y, b.z, b.w};
                #pragma unroll
                for (int r = 0; r < 4; ++r)
                    #pragma unroll
                    for (int c = 0; c < 4; ++c)
                        acc[r][c] += av[r] * bv[c];
            }
            __syncthreads();
        }
        #pragma unroll
        for (int r = 0; r < 4; ++r)
            #pragma unroll
            for (int c = 0; c < 4; ++c)
                zmax[r][c] = fmaxf(zmax[r][c], acc[r][c]);
    }
    #pragma unroll
    for (int r = 0; r < 4; ++r)
        #pragma unroll
        for (int c = 0; c < 4; ++c)
            g_part[((size_t)sc * BB + tb + r) * MD + m0 + tm + c] = zmax[r][c];
}

// ---------------- K4: final reduce + tanh + logits + log_softmax ------------
__global__ void head_kernel(const float* __restrict__ bmax,
                            const float* __restrict__ Wdoc,
                            const float* __restrict__ bdoc,
                            float* __restrict__ out) {
    __shared__ float ysh[MD];
    __shared__ float lsh[NC];
    const int b = blockIdx.x;
    const int t = threadIdx.x;
    for (int m = t; m < MD; m += 256) {
        float v = -3.402823466e38f;
        #pragma unroll 4
        for (int sc = 0; sc < NSC; ++sc)
            v = fmaxf(v, g_part[((size_t)sc * BB + b) * MD + m]);
        ysh[m] = tanhf(v + bmax[m]);
    }
    __syncthreads();
    const int w = t >> 5, lane = t & 31;
    for (int c = w; c < NC; c += 8) {
        float sum = 0.f;
        for (int m = lane; m < MD; m += 32)
            sum += ysh[m] * Wdoc[(size_t)c * MD + m];
        #pragma unroll
        for (int off = 16; off; off >>= 1)
            sum += __shfl_down_sync(0xffffffffu, sum, off);
        if (lane == 0) lsh[c] = sum + bdoc[c];
    }
    __syncthreads();
    if (t == 0) {
        float mx = lsh[0];
        for (int c = 1; c < NC; ++c) mx = fmaxf(mx, lsh[c]);
        float se = 0.f;
        for (int c = 0; c < NC; ++c) se += expf(lsh[c] - mx);
        float lse = logf(se) + mx;
        for (int c = 0; c < NC; ++c) out[b * NC + c] = lsh[c] - lse;
    }
}

// ---------------- launch -----------------------------------------------------
extern "C" void kernel_launch(void* const* d_in, const int* in_sizes, int n_in,
                              void* d_out, int out_size) {
    const int*   inp   = (const int*)  d_in[0];
    const float* table = (const float*)d_in[1];
    const float* cl0   = (const float*)d_in[2];
    const float* cr0   = (const float*)d_in[3];
    const float* Wl    = (const float*)d_in[4];
    const float* bl    = (const float*)d_in[5];
    const float* Wr    = (const float*)d_in[6];
    const float* br    = (const float*)d_in[7];
    const float* Wsl   = (const float*)d_in[8];
    const float* bsl   = (const float*)d_in[9];
    const float* Wsr   = (const float*)d_in[10];
    const float* bsr   = (const float*)d_in[11];
    const float* Wmax  = (const float*)d_in[12];
    const float* bmax  = (const float*)d_in[13];
    const float* Wdoc  = (const float*)d_in[14];
    const float* bdoc  = (const float*)d_in[15];
    float* out = (float*)d_out;

    gather_kernel<<<NROW, 128>>>(inp, table);
    init_ct_kernel<<<(HH * BB + 255) / 256, 256>>>(cl0, cr0);
    proj_kernel<<<dim3(NROW / 64, HH / 64), 256>>>(Wsl, bsl, Wsr, bsr);
    scan_kernel<<<128, 256>>>(Wl, bl, Wr, br);
    ymax_kernel<<<dim3(MD / 64, NSC), 256>>>(Wmax);
    head_kernel<<<BB, 256>>>(bmax, Wdoc, bdoc, out);
}

// round 2
// speedup vs baseline: 1.1874x; 1.1874x over previous
#include <cuda_runtime.h>
#include <math.h>

#define SS   512
#define BB   64
#define HH   512
#define EE   512
#define MD   1024
#define NC   20
#define BH   (BB*HH)     // 32768
#define NROW (SS*BB)     // 32768
#define NCH  256         // s-pair chunks in phase C (512 s / 2)

// ---------------- scratch (static device memory; no allocs) ----------------
__device__ float g_emb[(size_t)NROW*EE];   // gathered embeddings   [s][b][e]
__device__ float g_els[(size_t)NROW*HH];   // emb @ W_sl^T + b_sl   [s][b][h]
__device__ float g_ers[(size_t)NROW*HH];   // emb @ W_sr^T + b_sr   [s][b][h]
__device__ float g_cl [(size_t)NROW*HH];   // forward scan history  [s][b][h]
__device__ float g_cr [(size_t)NROW*HH];   // backward scan history [s][b][h]
__device__ float g_ctl[HH*BB];             // current fwd c, transposed [h][b]
__device__ float g_ctr[HH*BB];             // current bwd c, transposed [h][b]
__device__ float g_part[(size_t)NCH*BB*MD];// partial max of z      [ch][b][m]

__device__ unsigned g_bar_count;
__device__ volatile unsigned g_bar_gen;

// ---------------- software grid barrier (all CTAs wave-1 resident) ---------
__device__ __forceinline__ void grid_barrier() {
    __threadfence();
    __syncthreads();
    if (threadIdx.x == 0) {
        unsigned gen = g_bar_gen;
        if (atomicAdd(&g_bar_count, 1u) == gridDim.x - 1) {
            g_bar_count = 0;
            __threadfence();
            g_bar_gen = gen + 1;
        } else {
            while (g_bar_gen == gen) { }
        }
    }
    __syncthreads();
    __threadfence();
}

// ---------------- K0: embedding gather -------------------------------------
__global__ void gather_kernel(const int* __restrict__ inp,
                              const float* __restrict__ table) {
    int sb = blockIdx.x;
    int tok = inp[sb];
    const float4* src = reinterpret_cast<const float4*>(table + (size_t)tok * EE);
    float4* dst = reinterpret_cast<float4*>(g_emb + (size_t)sb * EE);
    dst[threadIdx.x] = src[threadIdx.x];
}

// ---------------- K0b: init transposed c state ------------------------------
__global__ void init_ct_kernel(const float* __restrict__ cl0,
                               const float* __restrict__ cr0) {
    int idx = blockIdx.x * blockDim.x + threadIdx.x;
    if (idx < HH * BB) {
        int k = idx >> 6;
        g_ctl[idx] = cl0[k];
        g_ctr[idx] = cr0[k];
    }
}

// ---------------- shared GEMM helpers ---------------------------------------
__device__ __forceinline__ void stor_frag(float (*S)[132], int k0, int row, float4 v) {
    S[k0+0][row] = v.x; S[k0+1][row] = v.y; S[k0+2][row] = v.z; S[k0+3][row] = v.w;
}

// ---------------- K1: projection GEMM  C = emb @ [Wsl;Wsr]^T ---------------
// rows = 32768, N = 1024 (first 512 -> els, next 512 -> ers), K = 512.
// 128x128 CTA tile, 8x8/thread, kk=16, double-buffered.
__global__ __launch_bounds__(256, 2)
void proj_kernel(const float* __restrict__ Wsl, const float* __restrict__ bsl,
                 const float* __restrict__ Wsr, const float* __restrict__ bsr) {
    __shared__ float As[2][16][132];
    __shared__ float Bs[2][16][132];
    const int row0 = blockIdx.x * 128;
    const int n0   = blockIdx.y * 128;
    const float* Bsrc = (n0 < 512) ? Wsl : Wsr;
    const float* bias = (n0 < 512) ? bsl : bsr;
    float* Out = (n0 < 512) ? g_els : g_ers;
    const int nb = n0 & 511;

    const int t  = threadIdx.x;
    const int tx = t & 15, ty = t >> 4;
    const int lr = t >> 2;           // loader row (0..63), second at +64
    const int kq = (t & 3) * 4;      // loader k quad

    float acc[8][8];
    #pragma unroll
    for (int i = 0; i < 8; ++i)
        #pragma unroll
        for (int j = 0; j < 8; ++j) acc[i][j] = 0.f;

    // stage 0 direct into smem buf 0
    {
        float4 a0 = *(const float4*)&g_emb[(size_t)(row0 + lr)      * EE + kq];
        float4 a1 = *(const float4*)&g_emb[(size_t)(row0 + lr + 64) * EE + kq];
        float4 b0 = *(const float4*)&Bsrc [(size_t)(nb  + lr)      * EE + kq];
        float4 b1 = *(const float4*)&Bsrc [(size_t)(nb  + lr + 64) * EE + kq];
        stor_frag(As[0], kq, lr,      a0);
        stor_frag(As[0], kq, lr + 64, a1);
        stor_frag(Bs[0], kq, lr,      b0);
        stor_frag(Bs[0], kq, lr + 64, b1);
    }
    __syncthreads();

    const int NSTG = EE / 16;   // 32
    int buf = 0;
    for (int sg = 0; sg < NSTG; ++sg) {
        float4 na0, na1, nb0, nb1;
        if (sg + 1 < NSTG) {
            int kc = (sg + 1) * 16;
            na0 = *(const float4*)&g_emb[(size_t)(row0 + lr)      * EE + kc + kq];
            na1 = *(const float4*)&g_emb[(size_t)(row0 + lr + 64) * EE + kc + kq];
            nb0 = *(const float4*)&Bsrc [(size_t)(nb  + lr)      * EE + kc + kq];
            nb1 = *(const float4*)&Bsrc [(size_t)(nb  + lr + 64) * EE + kc + kq];
        }
        #pragma unroll
        for (int kk = 0; kk < 16; ++kk) {
            float4 A0 = *(const float4*)&As[buf][kk][ty * 4];
            float4 A1 = *(const float4*)&As[buf][kk][ty * 4 + 64];
            float4 B0 = *(const float4*)&Bs[buf][kk][tx * 4];
            float4 B1 = *(const float4*)&Bs[buf][kk][tx * 4 + 64];
            float a[8] = {A0.x,A0.y,A0.z,A0.w,A1.x,A1.y,A1.z,A1.w};
            float b[8] = {B0.x,B0.y,B0.z,B0.w,B1.x,B1.y,B1.z,B1.w};
            #pragma unroll
            for (int i = 0; i < 8; ++i)
                #pragma unroll
                for (int j = 0; j < 8; ++j)
                    acc[i][j] += a[i] * b[j];
        }
        if (sg + 1 < NSTG) {
            stor_frag(As[buf^1], kq, lr,      na0);
            stor_frag(As[buf^1], kq, lr + 64, na1);
            stor_frag(Bs[buf^1], kq, lr,      nb0);
            stor_frag(Bs[buf^1], kq, lr + 64, nb1);
            __syncthreads();
            buf ^= 1;
        }
    }

    float bv[8];
    #pragma unroll
    for (int c = 0; c < 4; ++c) {
        bv[c]     = bias[nb + tx * 4 + c];
        bv[c + 4] = bias[nb + tx * 4 + 64 + c];
    }
    #pragma unroll
    for (int i = 0; i < 8; ++i) {
        int row = row0 + ty * 4 + (i < 4 ? i : 60 + i);
        float4 o0 = make_float4(acc[i][0]+bv[0], acc[i][1]+bv[1], acc[i][2]+bv[2], acc[i][3]+bv[3]);
        float4 o1 = make_float4(acc[i][4]+bv[4], acc[i][5]+bv[5], acc[i][6]+bv[6], acc[i][7]+bv[7]);
        *(float4*)&Out[(size_t)row * HH + nb + tx * 4]      = o0;
        *(float4*)&Out[(size_t)row * HH + nb + tx * 4 + 64] = o1;
    }
}

// ---------------- K2: persistent bidirectional scan (unchanged) ------------
__global__ void scan_kernel(const float* __restrict__ Wl, const float* __restrict__ bl,
                            const float* __restrict__ Wr, const float* __restrict__ br) {
    __shared__ float Wsh[HH][8];
    __shared__ float part[4][520];

    const int dir = (blockIdx.x >= 64);
    const int cb  = (blockIdx.x & 63) * 8;
    const float* W    = dir ? Wr    : Wl;
    const float* bias = dir ? br    : bl;
    const float* e    = dir ? g_ers : g_els;
    float* ct   = dir ? g_ctr : g_ctl;
    float* hist = dir ? g_cr  : g_cl;

    const int t = threadIdx.x;
    for (int i = t; i < 8 * HH; i += 256) {
        int jl = i >> 9;
        int k  = i & 511;
        Wsh[k][jl] = W[(size_t)(cb + jl) * HH + k];
    }
    const int kg    = t >> 6;
    const int t6    = t & 63;
    const int jl0   = (t6 & 3) * 2;
    const int bg    = t6 >> 2;
    const int kbase = kg * 128;
    const float4* cv = reinterpret_cast<const float4*>(ct);
    __syncthreads();

    for (int step = 0; step < SS; ++step) {
        const int s = dir ? (SS - 1 - step) : step;
        float a00=0.f,a01=0.f,a10=0.f,a11=0.f,a20=0.f,a21=0.f,a30=0.f,a31=0.f;
        #pragma unroll 8
        for (int k = 0; k < 128; ++k) {
            int kk = kbase + k;
            float4 c4 = __ldcg(&cv[kk * 16 + bg]);
            float2 w2 = *reinterpret_cast<const float2*>(&Wsh[kk][jl0]);
            a00 += c4.x * w2.x;  a01 += c4.x * w2.y;
            a10 += c4.y * w2.x;  a11 += c4.y * w2.y;
            a20 += c4.z * w2.x;  a21 += c4.z * w2.y;
            a30 += c4.w * w2.x;  a31 += c4.w * w2.y;
        }
        const int ob0 = bg * 4;
        part[kg][(jl0+0)*65 + ob0+0] = a00;  part[kg][(jl0+1)*65 + ob0+0] = a01;
        part[kg][(jl0+0)*65 + ob0+1] = a10;  part[kg][(jl0+1)*65 + ob0+1] = a11;
        part[kg][(jl0+0)*65 + ob0+2] = a20;  part[kg][(jl0+1)*65 + ob0+2] = a21;
        part[kg][(jl0+0)*65 + ob0+3] = a30;  part[kg][(jl0+1)*65 + ob0+3] = a31;
        __syncthreads();

        for (int o = t; o < 512; o += 256) {
            int ob = o >> 3, oj = o & 7;
            int pi = oj * 65 + ob;
            float v = part[0][pi] + part[1][pi] + part[2][pi] + part[3][pi];
            v += bias[cb + oj] + e[(size_t)s * BH + (size_t)ob * HH + cb + oj];
            v = tanhf(v);
            hist[(size_t)s * BH + (size_t)ob * HH + cb + oj] = v;
            ct[(size_t)(cb + oj) * BB + ob] = v;
        }
        grid_barrier();
    }
}

// ---------------- K3: z = cat @ Wmax^T with max folded over s-pairs ---------
// grid = (8 m-tiles, 256 s-pairs). 128 rows = 2 s x 64 b; rows i and i+64 of a
// tile share b, so per-thread acc[i][j] vs acc[i+4][j] is the s-max. tanh is
// monotonic -> defer tanh to the head kernel.
__global__ __launch_bounds__(256, 2)
void ymax_kernel(const float* __restrict__ Wmax) {
    __shared__ float As[2][16][132];
    __shared__ float Bs[2][16][132];
    const int m0 = blockIdx.x * 128;
    const int r0 = blockIdx.y * 128;        // s-pair base row

    const int t  = threadIdx.x;
    const int tx = t & 15, ty = t >> 4;
    const int lr = t >> 2;
    const int kq = (t & 3) * 4;

    float acc[8][8];
    #pragma unroll
    for (int i = 0; i < 8; ++i)
        #pragma unroll
        for (int j = 0; j < 8; ++j) acc[i][j] = 0.f;

    // stage 0
    {
        const float* Asrc = g_cl;  // kc=0 -> sel 0
        float4 a0 = *(const float4*)&Asrc[(size_t)(r0 + lr)      * 512 + kq];
        float4 a1 = *(const float4*)&Asrc[(size_t)(r0 + lr + 64) * 512 + kq];
        float4 b0 = *(const float4*)&Wmax[(size_t)(m0 + lr)      * 1536 + kq];
        float4 b1 = *(const float4*)&Wmax[(size_t)(m0 + lr + 64) * 1536 + kq];
        stor_frag(As[0], kq, lr,      a0);
        stor_frag(As[0], kq, lr + 64, a1);
        stor_frag(Bs[0], kq, lr,      b0);
        stor_frag(Bs[0], kq, lr + 64, b1);
    }
    __syncthreads();

    const int NSTG = 1536 / 16;   // 96
    int buf = 0;
    for (int sg = 0; sg < NSTG; ++sg) {
        float4 na0, na1, nb0, nb1;
        if (sg + 1 < NSTG) {
            int kc  = (sg + 1) * 16;
            int sel = kc >> 9;
            const float* Asrc = (sel == 0) ? g_cl : (sel == 1) ? g_emb : g_cr;
            int col = (kc & 511) + kq;
            na0 = *(const float4*)&Asrc[(size_t)(r0 + lr)      * 512 + col];
            na1 = *(const float4*)&Asrc[(size_t)(r0 + lr + 64) * 512 + col];
            nb0 = *(const float4*)&Wmax[(size_t)(m0 + lr)      * 1536 + kc + kq];
            nb1 = *(const float4*)&Wmax[(size_t)(m0 + lr + 64) * 1536 + kc + kq];
        }
        #pragma unroll
        for (int kk = 0; kk < 16; ++kk) {
            float4 A0 = *(const float4*)&As[buf][kk][ty * 4];
            float4 A1 = *(const float4*)&As[buf][kk][ty * 4 + 64];
            float4 B0 = *(const float4*)&Bs[buf][kk][tx * 4];
            float4 B1 = *(const float4*)&Bs[buf][kk][tx * 4 + 64];
            float a[8] = {A0.x,A0.y,A0.z,A0.w,A1.x,A1.y,A1.z,A1.w};
            float b[8] = {B0.x,B0.y,B0.z,B0.w,B1.x,B1.y,B1.z,B1.w};
            #pragma unroll
            for (int i = 0; i < 8; ++i)
                #pragma unroll
                for (int j = 0; j < 8; ++j)
                    acc[i][j] += a[i] * b[j];
        }
        if (sg + 1 < NSTG) {
            stor_frag(As[buf^1], kq, lr,      na0);
            stor_frag(As[buf^1], kq, lr + 64, na1);
            stor_frag(Bs[buf^1], kq, lr,      nb0);
            stor_frag(Bs[buf^1], kq, lr + 64, nb1);
            __syncthreads();
            buf ^= 1;
        }
    }

    // epilogue: max over the 2 s in this tile; rows i (s0) and i+4 (s1) share b
    const size_t chb = ((size_t)blockIdx.y * BB) * MD;
    #pragma unroll
    for (int i = 0; i < 4; ++i) {
        int b = ty * 4 + i;
        float4 o0 = make_float4(fmaxf(acc[i][0],acc[i+4][0]), fmaxf(acc[i][1],acc[i+4][1]),
                                fmaxf(acc[i][2],acc[i+4][2]), fmaxf(acc[i][3],acc[i+4][3]));
        float4 o1 = make_float4(fmaxf(acc[i][4],acc[i+4][4]), fmaxf(acc[i][5],acc[i+4][5]),
                                fmaxf(acc[i][6],acc[i+4][6]), fmaxf(acc[i][7],acc[i+4][7]));
        *(float4*)&g_part[chb + (size_t)b * MD + m0 + tx * 4]      = o0;
        *(float4*)&g_part[chb + (size_t)b * MD + m0 + tx * 4 + 64] = o1;
    }
}

// ---------------- K4: final reduce + tanh + logits + log_softmax ------------
__global__ void head_kernel(const float* __restrict__ bmax,
                            const float* __restrict__ Wdoc,
                            const float* __restrict__ bdoc,
                            float* __restrict__ out) {
    __shared__ float ysh[MD];
    __shared__ float lsh[NC];
    const int b = blockIdx.x;
    const int t = threadIdx.x;
    for (int m = t; m < MD; m += 256) {
        float v = -3.402823466e38f;
        for (int ch = 0; ch < NCH; ++ch)
            v = fmaxf(v, g_part[((size_t)ch * BB + b) * MD + m]);
        ysh[m] = tanhf(v + bmax[m]);
    }
    __syncthreads();
    const int w = t >> 5, lane = t & 31;
    for (int c = w; c < NC; c += 8) {
        float sum = 0.f;
        for (int m = lane; m < MD; m += 32)
            sum += ysh[m] * Wdoc[(size_t)c * MD + m];
        #pragma unroll
        for (int off = 16; off; off >>= 1)
            sum += __shfl_down_sync(0xffffffffu, sum, off);
        if (lane == 0) lsh[c] = sum + bdoc[c];
    }
    __syncthreads();
    if (t == 0) {
        float mx = lsh[0];
        for (int c = 1; c < NC; ++c) mx = fmaxf(mx, lsh[c]);
        float se = 0.f;
        for (int c = 0; c < NC; ++c) se += expf(lsh[c] - mx);
        float lse = logf(se) + mx;
        for (int c = 0; c < NC; ++c) out[b * NC + c] = lsh[c] - lse;
    }
}

// ---------------- launch -----------------------------------------------------
extern "C" void kernel_launch(void* const* d_in, const int* in_sizes, int n_in,
                              void* d_out, int out_size) {
    const int*   inp   = (const int*)  d_in[0];
    const float* table = (const float*)d_in[1];
    const float* cl0   = (const float*)d_in[2];
    const float* cr0   = (const float*)d_in[3];
    const float* Wl    = (const float*)d_in[4];
    const float* bl    = (const float*)d_in[5];
    const float* Wr    = (const float*)d_in[6];
    const float* br    = (const float*)d_in[7];
    const float* Wsl   = (const float*)d_in[8];
    const float* bsl   = (const float*)d_in[9];
    const float* Wsr   = (const float*)d_in[10];
    const float* bsr   = (const float*)d_in[11];
    const float* Wmax  = (const float*)d_in[12];
    const float* bmax  = (const float*)d_in[13];
    const float* Wdoc  = (const float*)d_in[14];
    const float* bdoc  = (const float*)d_in[15];
    float* out = (float*)d_out;

    gather_kernel<<<NROW, 128>>>(inp, table);
    init_ct_kernel<<<(HH * BB + 255) / 256, 256>>>(cl0, cr0);
    proj_kernel<<<dim3(NROW / 128, 1024 / 128), 256>>>(Wsl, bsl, Wsr, bsr);
    scan_kernel<<<128, 256>>>(Wl, bl, Wr, br);
    ymax_kernel<<<dim3(MD / 128, NCH), 256>>>(Wmax);
    head_kernel<<<BB, 256>>>(bmax, Wdoc, bdoc, out);
}

// round 3
// speedup vs baseline: 3.0469x; 2.5661x over previous
#include <cuda_runtime.h>
#include <math.h>
#include <stdint.h>

#define SS   512
#define BB   64
#define HH   512
#define EE   512
#define MD   1024
#define NC   20
#define BH   (BB*HH)     // 32768
#define NROW (SS*BB)     // 32768
#define NCH  256         // s-pair chunks in phase C

// ---------------- scratch (static device memory; no allocs) ----------------
__device__ float g_emb[(size_t)NROW*EE];   // gathered embeddings   [s][b][e]
__device__ float g_els[(size_t)NROW*HH];   // emb @ W_sl^T + b_sl   [s][b][h]
__device__ float g_ers[(size_t)NROW*HH];   // emb @ W_sr^T + b_sr   [s][b][h]
__device__ float g_cl [(size_t)NROW*HH];   // forward scan history  [s][b][h]
__device__ float g_cr [(size_t)NROW*HH];   // backward scan history [s][b][h]
__device__ float g_part[(size_t)NCH*BB*MD];// partial max of z      [ch][b][m]

// ---------------- helpers ----------------------------------------------------
__device__ __forceinline__ uint32_t s2u(const void* p) {
    uint32_t a;
    asm("{ .reg .u64 t; cvta.to.shared.u64 t, %1; cvt.u32.u64 %0, t; }"
        : "=r"(a) : "l"(p));
    return a;
}
#define CLUSTER_SYNC() do { \
    asm volatile("barrier.cluster.arrive.aligned;" ::: "memory"); \
    asm volatile("barrier.cluster.wait.aligned;"   ::: "memory"); } while (0)

// ---------------- K0: embedding gather -------------------------------------
__global__ void gather_kernel(const int* __restrict__ inp,
                              const float* __restrict__ table) {
    int sb = blockIdx.x;
    int tok = inp[sb];
    const float4* src = reinterpret_cast<const float4*>(table + (size_t)tok * EE);
    float4* dst = reinterpret_cast<float4*>(g_emb + (size_t)sb * EE);
    dst[threadIdx.x] = src[threadIdx.x];
}

// ---------------- shared GEMM helpers ---------------------------------------
__device__ __forceinline__ void stor_frag(float (*S)[132], int k0, int row, float4 v) {
    S[k0+0][row] = v.x; S[k0+1][row] = v.y; S[k0+2][row] = v.z; S[k0+3][row] = v.w;
}

// ---------------- K1: projection GEMM  C = emb @ [Wsl;Wsr]^T ---------------
__global__ __launch_bounds__(256, 2)
void proj_kernel(const float* __restrict__ Wsl, const float* __restrict__ bsl,
                 const float* __restrict__ Wsr, const float* __restrict__ bsr) {
    __shared__ float As[2][16][132];
    __shared__ float Bs[2][16][132];
    const int row0 = blockIdx.x * 128;
    const int n0   = blockIdx.y * 128;
    const float* Bsrc = (n0 < 512) ? Wsl : Wsr;
    const float* bias = (n0 < 512) ? bsl : bsr;
    float* Out = (n0 < 512) ? g_els : g_ers;
    const int nb = n0 & 511;

    const int t  = threadIdx.x;
    const int tx = t & 15, ty = t >> 4;
    const int lr = t >> 2;
    const int kq = (t & 3) * 4;

    float acc[8][8];
    #pragma unroll
    for (int i = 0; i < 8; ++i)
        #pragma unroll
        for (int j = 0; j < 8; ++j) acc[i][j] = 0.f;

    {
        float4 a0 = *(const float4*)&g_emb[(size_t)(row0 + lr)      * EE + kq];
        float4 a1 = *(const float4*)&g_emb[(size_t)(row0 + lr + 64) * EE + kq];
        float4 b0 = *(const float4*)&Bsrc [(size_t)(nb  + lr)      * EE + kq];
        float4 b1 = *(const float4*)&Bsrc [(size_t)(nb  + lr + 64) * EE + kq];
        stor_frag(As[0], kq, lr,      a0);
        stor_frag(As[0], kq, lr + 64, a1);
        stor_frag(Bs[0], kq, lr,      b0);
        stor_frag(Bs[0], kq, lr + 64, b1);
    }
    __syncthreads();

    const int NSTG = EE / 16;
    int buf = 0;
    for (int sg = 0; sg < NSTG; ++sg) {
        float4 na0, na1, nb0, nb1;
        if (sg + 1 < NSTG) {
            int kc = (sg + 1) * 16;
            na0 = *(const float4*)&g_emb[(size_t)(row0 + lr)      * EE + kc + kq];
            na1 = *(const float4*)&g_emb[(size_t)(row0 + lr + 64) * EE + kc + kq];
            nb0 = *(const float4*)&Bsrc [(size_t)(nb  + lr)      * EE + kc + kq];
            nb1 = *(const float4*)&Bsrc [(size_t)(nb  + lr + 64) * EE + kc + kq];
        }
        #pragma unroll
        for (int kk = 0; kk < 16; ++kk) {
            float4 A0 = *(const float4*)&As[buf][kk][ty * 4];
            float4 A1 = *(const float4*)&As[buf][kk][ty * 4 + 64];
            float4 B0 = *(const float4*)&Bs[buf][kk][tx * 4];
            float4 B1 = *(const float4*)&Bs[buf][kk][tx * 4 + 64];
            float a[8] = {A0.x,A0.y,A0.z,A0.w,A1.x,A1.y,A1.z,A1.w};
            float b[8] = {B0.x,B0.y,B0.z,B0.w,B1.x,B1.y,B1.z,B1.w};
            #pragma unroll
            for (int i = 0; i < 8; ++i)
                #pragma unroll
                for (int j = 0; j < 8; ++j)
                    acc[i][j] += a[i] * b[j];
        }
        if (sg + 1 < NSTG) {
            stor_frag(As[buf^1], kq, lr,      na0);
            stor_frag(As[buf^1], kq, lr + 64, na1);
            stor_frag(Bs[buf^1], kq, lr,      nb0);
            stor_frag(Bs[buf^1], kq, lr + 64, nb1);
            __syncthreads();
            buf ^= 1;
        }
    }

    float bv[8];
    #pragma unroll
    for (int c = 0; c < 4; ++c) {
        bv[c]     = bias[nb + tx * 4 + c];
        bv[c + 4] = bias[nb + tx * 4 + 64 + c];
    }
    #pragma unroll
    for (int i = 0; i < 8; ++i) {
        int row = row0 + ty * 4 + (i < 4 ? i : 60 + i);
        float4 o0 = make_float4(acc[i][0]+bv[0], acc[i][1]+bv[1], acc[i][2]+bv[2], acc[i][3]+bv[3]);
        float4 o1 = make_float4(acc[i][4]+bv[4], acc[i][5]+bv[5], acc[i][6]+bv[6], acc[i][7]+bv[7]);
        *(float4*)&Out[(size_t)row * HH + nb + tx * 4]      = o0;
        *(float4*)&Out[(size_t)row * HH + nb + tx * 4 + 64] = o1;
    }
}

// ---------------- K2: clustered bidirectional scan (NO grid barrier) --------
// 16 clusters x 8 CTAs. cluster = (dir, 8-batch group); rank owns 64 j-cols.
// W-slice [64j x 512k] lives in smem; c-state [512k x 8b] double-buffered in
// smem and replicated cluster-wide via DSMEM pushes + one cluster.sync/step.
#define SCAN_W_FLT    (64*512)          // 32768
#define SCAN_C_FLT    (512*8)           // 4096
#define SCAN_P_FLT    (8*8*68)          // 4352
#define SCAN_SMEM_FLT (SCAN_W_FLT + 2*SCAN_C_FLT + SCAN_P_FLT + 64)
#define SCAN_SMEM_BYTES (SCAN_SMEM_FLT*4)

__global__ void __cluster_dims__(8, 1, 1) __launch_bounds__(256, 1)
scan_kernel(const float* __restrict__ Wl, const float* __restrict__ bl,
            const float* __restrict__ Wr, const float* __restrict__ br,
            const float* __restrict__ cl0, const float* __restrict__ cr0) {
    extern __shared__ float sm[];
    float* Wsh  = sm;                         // [512][64]  (k-major)
    float* cshA = sm + SCAN_W_FLT;            // [512][8]
    float* cshB = cshA + SCAN_C_FLT;          // [512][8]
    float* part = cshB + SCAN_C_FLT;          // [8 kg][8 b][68]
    float* bsh  = part + SCAN_P_FLT;          // [64]

    const int cid = blockIdx.x >> 3;
    const int rnk = blockIdx.x & 7;
    const int dir = cid & 1;
    const int b0  = (cid >> 1) * 8;
    const int j0  = rnk * 64;

    const float* W    = dir ? Wr  : Wl;
    const float* bias = dir ? br  : bl;
    const float* c0   = dir ? cr0 : cl0;
    const float* e    = dir ? g_ers : g_els;
    float* hist       = dir ? g_cr  : g_cl;

    const int t = threadIdx.x;
    // W slice: Wsh[k][jl] = W[(j0+jl)*512 + k]
    for (int i = t; i < SCAN_W_FLT; i += 256) {
        int jl = i >> 9, k = i & 511;
        Wsh[k * 64 + jl] = W[(size_t)(j0 + jl) * 512 + k];
    }
    if (t < 64) bsh[t] = bias[j0 + t];
    for (int i = t; i < SCAN_C_FLT; i += 256)
        cshA[i] = c0[i >> 3];
    __syncthreads();
    CLUSTER_SYNC();                           // peers ready before DSMEM pushes

    const int kg = t >> 5;                    // warp = k-group (64 k each)
    const int jq = t & 15;                    // j quad
    const int bq = (t >> 4) & 1;              // b quad
    const int kbase = kg * 64;
    // reducer outputs: o = bi*64 + jl
    const int bi1 = t >> 6,          jl1 = t & 63;
    const int bi2 = (t + 256) >> 6,  jl2 = t & 63;

    float* cur = cshA;
    float* nxt = cshB;

    for (int step = 0; step < SS; ++step) {
        const int s = dir ? (SS - 1 - step) : step;
        const size_t ebase = (size_t)s * BH;
        // prefetch this thread's two e values (used after the k-loop)
        float e1 = __ldcg(&e[ebase + (size_t)(b0 + bi1) * 512 + j0 + jl1]);
        float e2 = __ldcg(&e[ebase + (size_t)(b0 + bi2) * 512 + j0 + jl2]);

        float acc[4][4];
        #pragma unroll
        for (int i = 0; i < 4; ++i)
            #pragma unroll
            for (int j = 0; j < 4; ++j) acc[i][j] = 0.f;

        const float* cp = cur + (size_t)kbase * 8 + bq * 4;
        const float* wp = Wsh + (size_t)kbase * 64 + jq * 4;
        #pragma unroll 8
        for (int k = 0; k < 64; ++k) {
            float4 c4 = *(const float4*)(cp + k * 8);
            float4 w4 = *(const float4*)(wp + k * 64);
            acc[0][0] += c4.x*w4.x; acc[0][1] += c4.x*w4.y; acc[0][2] += c4.x*w4.z; acc[0][3] += c4.x*w4.w;
            acc[1][0] += c4.y*w4.x; acc[1][1] += c4.y*w4.y; acc[1][2] += c4.y*w4.z; acc[1][3] += c4.y*w4.w;
            acc[2][0] += c4.z*w4.x; acc[2][1] += c4.z*w4.y; acc[2][2] += c4.z*w4.z; acc[2][3] += c4.z*w4.w;
            acc[3][0] += c4.w*w4.x; acc[3][1] += c4.w*w4.y; acc[3][2] += c4.w*w4.z; acc[3][3] += c4.w*w4.w;
        }
        #pragma unroll
        for (int bb = 0; bb < 4; ++bb) {
            int b = bq * 4 + bb;
            *(float4*)&part[(kg * 8 + b) * 68 + jq * 4] =
                make_float4(acc[bb][0], acc[bb][1], acc[bb][2], acc[bb][3]);
        }
        __syncthreads();

        const uint32_t nxt_u = s2u(nxt);
        #pragma unroll
        for (int h = 0; h < 2; ++h) {
            const int bi = h ? bi2 : bi1;
            const int jl = h ? jl2 : jl1;
            float v = 0.f;
            #pragma unroll
            for (int g = 0; g < 8; ++g) v += part[(g * 8 + bi) * 68 + jl];
            v = tanhf(v + bsh[jl] + (h ? e2 : e1));
            hist[ebase + (size_t)(b0 + bi) * 512 + j0 + jl] = v;
            const uint32_t loc = nxt_u + (uint32_t)(((j0 + jl) * 8 + bi) * 4);
            const uint32_t vv  = __float_as_uint(v);
            #pragma unroll
            for (int rr = 0; rr < 8; ++rr) {
                uint32_t rem;
                asm("mapa.shared::cluster.u32 %0, %1, %2;" : "=r"(rem) : "r"(loc), "r"(rr));
                asm volatile("st.shared::cluster.b32 [%0], %1;" :: "r"(rem), "r"(vv) : "memory");
            }
        }
        CLUSTER_SYNC();   // full block+cluster sync: publishes visible, part reusable
        float* tmp = cur; cur = nxt; nxt = tmp;
    }
}

// ---------------- K3: z = cat @ Wmax^T with max folded over s-pairs ---------
__global__ __launch_bounds__(256, 2)
void ymax_kernel(const float* __restrict__ Wmax) {
    __shared__ float As[2][16][132];
    __shared__ float Bs[2][16][132];
    const int m0 = blockIdx.x * 128;
    const int r0 = blockIdx.y * 128;

    const int t  = threadIdx.x;
    const int tx = t & 15, ty = t >> 4;
    const int lr = t >> 2;
    const int kq = (t & 3) * 4;

    float acc[8][8];
    #pragma unroll
    for (int i = 0; i < 8; ++i)
        #pragma unroll
        for (int j = 0; j < 8; ++j) acc[i][j] = 0.f;

    {
        const float* Asrc = g_cl;
        float4 a0 = *(const float4*)&Asrc[(size_t)(r0 + lr)      * 512 + kq];
        float4 a1 = *(const float4*)&Asrc[(size_t)(r0 + lr + 64) * 512 + kq];
        float4 b0 = *(const float4*)&Wmax[(size_t)(m0 + lr)      * 1536 + kq];
        float4 b1 = *(const float4*)&Wmax[(size_t)(m0 + lr + 64) * 1536 + kq];
        stor_frag(As[0], kq, lr,      a0);
        stor_frag(As[0], kq, lr + 64, a1);
        stor_frag(Bs[0], kq, lr,      b0);
        stor_frag(Bs[0], kq, lr + 64, b1);
    }
    __syncthreads();

    const int NSTG = 1536 / 16;
    int buf = 0;
    for (int sg = 0; sg < NSTG; ++sg) {
        float4 na0, na1, nb0, nb1;
        if (sg + 1 < NSTG) {
            int kc  = (sg + 1) * 16;
            int sel = kc >> 9;
            const float* Asrc = (sel == 0) ? g_cl : (sel == 1) ? g_emb : g_cr;
            int col = (kc & 511) + kq;
            na0 = *(const float4*)&Asrc[(size_t)(r0 + lr)      * 512 + col];
            na1 = *(const float4*)&Asrc[(size_t)(r0 + lr + 64) * 512 + col];
            nb0 = *(const float4*)&Wmax[(size_t)(m0 + lr)      * 1536 + kc + kq];
            nb1 = *(const float4*)&Wmax[(size_t)(m0 + lr + 64) * 1536 + kc + kq];
        }
        #pragma unroll
        for (int kk = 0; kk < 16; ++kk) {
            float4 A0 = *(const float4*)&As[buf][kk][ty * 4];
            float4 A1 = *(const float4*)&As[buf][kk][ty * 4 + 64];
            float4 B0 = *(const float4*)&Bs[buf][kk][tx * 4];
            float4 B1 = *(const float4*)&Bs[buf][kk][tx * 4 + 64];
            float a[8] = {A0.x,A0.y,A0.z,A0.w,A1.x,A1.y,A1.z,A1.w};
            float b[8] = {B0.x,B0.y,B0.z,B0.w,B1.x,B1.y,B1.z,B1.w};
            #pragma unroll
            for (int i = 0; i < 8; ++i)
                #pragma unroll
                for (int j = 0; j < 8; ++j)
                    acc[i][j] += a[i] * b[j];
        }
        if (sg + 1 < NSTG) {
            stor_frag(As[buf^1], kq, lr,      na0);
            stor_frag(As[buf^1], kq, lr + 64, na1);
            stor_frag(Bs[buf^1], kq, lr,      nb0);
            stor_frag(Bs[buf^1], kq, lr + 64, nb1);
            __syncthreads();
            buf ^= 1;
        }
    }

    const size_t chb = ((size_t)blockIdx.y * BB) * MD;
    #pragma unroll
    for (int i = 0; i < 4; ++i) {
        int b = ty * 4 + i;
        float4 o0 = make_float4(fmaxf(acc[i][0],acc[i+4][0]), fmaxf(acc[i][1],acc[i+4][1]),
                                fmaxf(acc[i][2],acc[i+4][2]), fmaxf(acc[i][3],acc[i+4][3]));
        float4 o1 = make_float4(fmaxf(acc[i][4],acc[i+4][4]), fmaxf(acc[i][5],acc[i+4][5]),
                                fmaxf(acc[i][6],acc[i+4][6]), fmaxf(acc[i][7],acc[i+4][7]));
        *(float4*)&g_part[chb + (size_t)b * MD + m0 + tx * 4]      = o0;
        *(float4*)&g_part[chb + (size_t)b * MD + m0 + tx * 4 + 64] = o1;
    }
}

// ---------------- K4: final reduce + tanh + logits + log_softmax ------------
__global__ void head_kernel(const float* __restrict__ bmax,
                            const float* __restrict__ Wdoc,
                            const float* __restrict__ bdoc,
                            float* __restrict__ out) {
    __shared__ float ysh[MD];
    __shared__ float lsh[NC];
    const int b = blockIdx.x;
    const int t = threadIdx.x;
    for (int m = t; m < MD; m += 256) {
        float v = -3.402823466e38f;
        for (int ch = 0; ch < NCH; ++ch)
            v = fmaxf(v, g_part[((size_t)ch * BB + b) * MD + m]);
        ysh[m] = tanhf(v + bmax[m]);
    }
    __syncthreads();
    const int w = t >> 5, lane = t & 31;
    for (int c = w; c < NC; c += 8) {
        float sum = 0.f;
        for (int m = lane; m < MD; m += 32)
            sum += ysh[m] * Wdoc[(size_t)c * MD + m];
        #pragma unroll
        for (int off = 16; off; off >>= 1)
            sum += __shfl_down_sync(0xffffffffu, sum, off);
        if (lane == 0) lsh[c] = sum + bdoc[c];
    }
    __syncthreads();
    if (t == 0) {
        float mx = lsh[0];
        for (int c = 1; c < NC; ++c) mx = fmaxf(mx, lsh[c]);
        float se = 0.f;
        for (int c = 0; c < NC; ++c) se += expf(lsh[c] - mx);
        float lse = logf(se) + mx;
        for (int c = 0; c < NC; ++c) out[b * NC + c] = lsh[c] - lse;
    }
}

// ---------------- launch -----------------------------------------------------
extern "C" void kernel_launch(void* const* d_in, const int* in_sizes, int n_in,
                              void* d_out, int out_size) {
    const int*   inp   = (const int*)  d_in[0];
    const float* table = (const float*)d_in[1];
    const float* cl0   = (const float*)d_in[2];
    const float* cr0   = (const float*)d_in[3];
    const float* Wl    = (const float*)d_in[4];
    const float* bl    = (const float*)d_in[5];
    const float* Wr    = (const float*)d_in[6];
    const float* br    = (const float*)d_in[7];
    const float* Wsl   = (const float*)d_in[8];
    const float* bsl   = (const float*)d_in[9];
    const float* Wsr   = (const float*)d_in[10];
    const float* bsr   = (const float*)d_in[11];
    const float* Wmax  = (const float*)d_in[12];
    const float* bmax  = (const float*)d_in[13];
    const float* Wdoc  = (const float*)d_in[14];
    const float* bdoc  = (const float*)d_in[15];
    float* out = (float*)d_out;

    cudaFuncSetAttribute(scan_kernel,
                         cudaFuncAttributeMaxDynamicSharedMemorySize,
                         SCAN_SMEM_BYTES);

    gather_kernel<<<NROW, 128>>>(inp, table);
    proj_kernel<<<dim3(NROW / 128, 1024 / 128), 256>>>(Wsl, bsl, Wsr, bsr);
    scan_kernel<<<128, 256, SCAN_SMEM_BYTES>>>(Wl, bl, Wr, br, cl0, cr0);
    ymax_kernel<<<dim3(MD / 128, NCH), 256>>>(Wmax);
    head_kernel<<<BB, 256>>>(bmax, Wdoc, bdoc, out);
}

// round 4
// speedup vs baseline: 3.1303x; 1.0274x over previous
#include <cuda_runtime.h>
#include <math.h>
#include <stdint.h>

#define SS   512
#define BB   64
#define HH   512
#define EE   512
#define MD   1024
#define NC   20
#define BH   (BB*HH)     // 32768
#define NROW (SS*BB)     // 32768
#define NCH  256         // s-pair chunks in phase C

// ---------------- scratch (static device memory; no allocs) ----------------
__device__ float g_emb[(size_t)NROW*EE];
__device__ float g_els[(size_t)NROW*HH];
__device__ float g_ers[(size_t)NROW*HH];
__device__ float g_cl [(size_t)NROW*HH];
__device__ float g_cr [(size_t)NROW*HH];
__device__ float g_part[(size_t)NCH*BB*MD];

// ---------------- helpers ----------------------------------------------------
__device__ __forceinline__ uint32_t s2u(const void* p) {
    uint32_t a;
    asm("{ .reg .u64 t; cvta.to.shared.u64 t, %1; cvt.u32.u64 %0, t; }"
        : "=r"(a) : "l"(p));
    return a;
}
#define CLUSTER_SYNC() do { \
    asm volatile("barrier.cluster.arrive.aligned;" ::: "memory"); \
    asm volatile("barrier.cluster.wait.aligned;"   ::: "memory"); } while (0)

// packed fp32x2 FMA (FFMA2) — PTX-only on sm_103a, bit-exact fp32
__device__ __forceinline__ void ffma2(unsigned long long& d,
                                      unsigned long long a,
                                      unsigned long long b) {
    asm("fma.rn.f32x2 %0, %1, %2, %0;" : "+l"(d) : "l"(a), "l"(b));
}
__device__ __forceinline__ unsigned long long dup2(float x) {
    unsigned long long r;
    asm("mov.b64 %0, {%1, %1};" : "=l"(r) : "f"(x));
    return r;
}
__device__ __forceinline__ float2 unpk(unsigned long long v) {
    float2 r;
    asm("mov.b64 {%0, %1}, %2;" : "=f"(r.x), "=f"(r.y) : "l"(v));
    return r;
}

// ---------------- K0: embedding gather -------------------------------------
__global__ void gather_kernel(const int* __restrict__ inp,
                              const float* __restrict__ table) {
    int sb = blockIdx.x;
    int tok = inp[sb];
    const float4* src = reinterpret_cast<const float4*>(table + (size_t)tok * EE);
    float4* dst = reinterpret_cast<float4*>(g_emb + (size_t)sb * EE);
    dst[threadIdx.x] = src[threadIdx.x];
}

// ---------------- shared GEMM helpers ---------------------------------------
__device__ __forceinline__ void stor_frag(float (*S)[132], int k0, int row, float4 v) {
    S[k0+0][row] = v.x; S[k0+1][row] = v.y; S[k0+2][row] = v.z; S[k0+3][row] = v.w;
}

// packed-FMA inner step shared by both GEMMs
__device__ __forceinline__ void mm_step(const float (*As)[132], const float (*Bs)[132],
                                        int kk, int ty, int tx,
                                        unsigned long long (*acc2)[4]) {
    float4 A0 = *(const float4*)&As[kk][ty * 4];
    float4 A1 = *(const float4*)&As[kk][ty * 4 + 64];
    ulonglong2 Bp0 = *(const ulonglong2*)&Bs[kk][tx * 4];
    ulonglong2 Bp1 = *(const ulonglong2*)&Bs[kk][tx * 4 + 64];
    unsigned long long bp[4] = {Bp0.x, Bp0.y, Bp1.x, Bp1.y};
    float a[8] = {A0.x, A0.y, A0.z, A0.w, A1.x, A1.y, A1.z, A1.w};
    #pragma unroll
    for (int i = 0; i < 8; ++i) {
        unsigned long long ad = dup2(a[i]);
        #pragma unroll
        for (int jp = 0; jp < 4; ++jp)
            ffma2(acc2[i][jp], ad, bp[jp]);
    }
}

// ---------------- K1: projection GEMM  C = emb @ [Wsl;Wsr]^T ---------------
__global__ __launch_bounds__(256, 2)
void proj_kernel(const float* __restrict__ Wsl, const float* __restrict__ bsl,
                 const float* __restrict__ Wsr, const float* __restrict__ bsr) {
    __shared__ float As[2][16][132];
    __shared__ float Bs[2][16][132];
    const int row0 = blockIdx.x * 128;
    const int n0   = blockIdx.y * 128;
    const float* Bsrc = (n0 < 512) ? Wsl : Wsr;
    const float* bias = (n0 < 512) ? bsl : bsr;
    float* Out = (n0 < 512) ? g_els : g_ers;
    const int nb = n0 & 511;

    const int t  = threadIdx.x;
    const int tx = t & 15, ty = t >> 4;
    const int lr = t >> 2;
    const int kq = (t & 3) * 4;

    unsigned long long acc2[8][4];
    #pragma unroll
    for (int i = 0; i < 8; ++i)
        #pragma unroll
        for (int j = 0; j < 4; ++j) acc2[i][j] = 0ull;

    {
        float4 a0 = *(const float4*)&g_emb[(size_t)(row0 + lr)      * EE + kq];
        float4 a1 = *(const float4*)&g_emb[(size_t)(row0 + lr + 64) * EE + kq];
        float4 b0 = *(const float4*)&Bsrc [(size_t)(nb  + lr)      * EE + kq];
        float4 b1 = *(const float4*)&Bsrc [(size_t)(nb  + lr + 64) * EE + kq];
        stor_frag(As[0], kq, lr,      a0);
        stor_frag(As[0], kq, lr + 64, a1);
        stor_frag(Bs[0], kq, lr,      b0);
        stor_frag(Bs[0], kq, lr + 64, b1);
    }
    __syncthreads();

    const int NSTG = EE / 16;
    int buf = 0;
    for (int sg = 0; sg < NSTG; ++sg) {
        float4 na0, na1, nb0, nb1;
        if (sg + 1 < NSTG) {
            int kc = (sg + 1) * 16;
            na0 = *(const float4*)&g_emb[(size_t)(row0 + lr)      * EE + kc + kq];
            na1 = *(const float4*)&g_emb[(size_t)(row0 + lr + 64) * EE + kc + kq];
            nb0 = *(const float4*)&Bsrc [(size_t)(nb  + lr)      * EE + kc + kq];
            nb1 = *(const float4*)&Bsrc [(size_t)(nb  + lr + 64) * EE + kc + kq];
        }
        #pragma unroll
        for (int kk = 0; kk < 16; ++kk)
            mm_step(As[buf], Bs[buf], kk, ty, tx, acc2);
        if (sg + 1 < NSTG) {
            stor_frag(As[buf^1], kq, lr,      na0);
            stor_frag(As[buf^1], kq, lr + 64, na1);
            stor_frag(Bs[buf^1], kq, lr,      nb0);
            stor_frag(Bs[buf^1], kq, lr + 64, nb1);
            __syncthreads();
            buf ^= 1;
        }
    }

    float bv[8];
    #pragma unroll
    for (int c = 0; c < 4; ++c) {
        bv[c]     = bias[nb + tx * 4 + c];
        bv[c + 4] = bias[nb + tx * 4 + 64 + c];
    }
    #pragma unroll
    for (int i = 0; i < 8; ++i) {
        int row = row0 + ty * 4 + (i < 4 ? i : 60 + i);
        float2 p0 = unpk(acc2[i][0]), p1 = unpk(acc2[i][1]);
        float2 p2 = unpk(acc2[i][2]), p3 = unpk(acc2[i][3]);
        float4 o0 = make_float4(p0.x+bv[0], p0.y+bv[1], p1.x+bv[2], p1.y+bv[3]);
        float4 o1 = make_float4(p2.x+bv[4], p2.y+bv[5], p3.x+bv[6], p3.y+bv[7]);
        *(float4*)&Out[(size_t)row * HH + nb + tx * 4]      = o0;
        *(float4*)&Out[(size_t)row * HH + nb + tx * 4 + 64] = o1;
    }
}

// ---------------- K2: clustered bidirectional scan (unchanged) --------------
#define SCAN_W_FLT    (64*512)
#define SCAN_C_FLT    (512*8)
#define SCAN_P_FLT    (8*8*68)
#define SCAN_SMEM_FLT (SCAN_W_FLT + 2*SCAN_C_FLT + SCAN_P_FLT + 64)
#define SCAN_SMEM_BYTES (SCAN_SMEM_FLT*4)

__global__ void __cluster_dims__(8, 1, 1) __launch_bounds__(256, 1)
scan_kernel(const float* __restrict__ Wl, const float* __restrict__ bl,
            const float* __restrict__ Wr, const float* __restrict__ br,
            const float* __restrict__ cl0, const float* __restrict__ cr0) {
    extern __shared__ float sm[];
    float* Wsh  = sm;
    float* cshA = sm + SCAN_W_FLT;
    float* cshB = cshA + SCAN_C_FLT;
    float* part = cshB + SCAN_C_FLT;
    float* bsh  = part + SCAN_P_FLT;

    const int cid = blockIdx.x >> 3;
    const int rnk = blockIdx.x & 7;
    const int dir = cid & 1;
    const int b0  = (cid >> 1) * 8;
    const int j0  = rnk * 64;

    const float* W    = dir ? Wr  : Wl;
    const float* bias = dir ? br  : bl;
    const float* c0   = dir ? cr0 : cl0;
    const float* e    = dir ? g_ers : g_els;
    float* hist       = dir ? g_cr  : g_cl;

    const int t = threadIdx.x;
    for (int i = t; i < SCAN_W_FLT; i += 256) {
        int jl = i >> 9, k = i & 511;
        Wsh[k * 64 + jl] = W[(size_t)(j0 + jl) * 512 + k];
    }
    if (t < 64) bsh[t] = bias[j0 + t];
    for (int i = t; i < SCAN_C_FLT; i += 256)
        cshA[i] = c0[i >> 3];
    __syncthreads();
    CLUSTER_SYNC();

    const int kg = t >> 5;
    const int jq = t & 15;
    const int bq = (t >> 4) & 1;
    const int kbase = kg * 64;
    const int bi1 = t >> 6,          jl1 = t & 63;
    const int bi2 = (t + 256) >> 6,  jl2 = t & 63;

    float* cur = cshA;
    float* nxt = cshB;

    for (int step = 0; step < SS; ++step) {
        const int s = dir ? (SS - 1 - step) : step;
        const size_t ebase = (size_t)s * BH;
        float e1 = __ldcg(&e[ebase + (size_t)(b0 + bi1) * 512 + j0 + jl1]);
        float e2 = __ldcg(&e[ebase + (size_t)(b0 + bi2) * 512 + j0 + jl2]);

        float acc[4][4];
        #pragma unroll
        for (int i = 0; i < 4; ++i)
            #pragma unroll
            for (int j = 0; j < 4; ++j) acc[i][j] = 0.f;

        const float* cp = cur + (size_t)kbase * 8 + bq * 4;
        const float* wp = Wsh + (size_t)kbase * 64 + jq * 4;
        #pragma unroll 8
        for (int k = 0; k < 64; ++k) {
            float4 c4 = *(const float4*)(cp + k * 8);
            float4 w4 = *(const float4*)(wp + k * 64);
            acc[0][0] += c4.x*w4.x; acc[0][1] += c4.x*w4.y; acc[0][2] += c4.x*w4.z; acc[0][3] += c4.x*w4.w;
            acc[1][0] += c4.y*w4.x; acc[1][1] += c4.y*w4.y; acc[1][2] += c4.y*w4.z; acc[1][3] += c4.y*w4.w;
            acc[2][0] += c4.z*w4.x; acc[2][1] += c4.z*w4.y; acc[2][2] += c4.z*w4.z; acc[2][3] += c4.z*w4.w;
            acc[3][0] += c4.w*w4.x; acc[3][1] += c4.w*w4.y; acc[3][2] += c4.w*w4.z; acc[3][3] += c4.w*w4.w;
        }
        #pragma unroll
        for (int bb = 0; bb < 4; ++bb) {
            int b = bq * 4 + bb;
            *(float4*)&part[(kg * 8 + b) * 68 + jq * 4] =
                make_float4(acc[bb][0], acc[bb][1], acc[bb][2], acc[bb][3]);
        }
        __syncthreads();

        const uint32_t nxt_u = s2u(nxt);
        #pragma unroll
        for (int h = 0; h < 2; ++h) {
            const int bi = h ? bi2 : bi1;
            const int jl = h ? jl2 : jl1;
            float v = 0.f;
            #pragma unroll
            for (int g = 0; g < 8; ++g) v += part[(g * 8 + bi) * 68 + jl];
            v = tanhf(v + bsh[jl] + (h ? e2 : e1));
            hist[ebase + (size_t)(b0 + bi) * 512 + j0 + jl] = v;
            const uint32_t loc = nxt_u + (uint32_t)(((j0 + jl) * 8 + bi) * 4);
            const uint32_t vv  = __float_as_uint(v);
            #pragma unroll
            for (int rr = 0; rr < 8; ++rr) {
                uint32_t rem;
                asm("mapa.shared::cluster.u32 %0, %1, %2;" : "=r"(rem) : "r"(loc), "r"(rr));
                asm volatile("st.shared::cluster.b32 [%0], %1;" :: "r"(rem), "r"(vv) : "memory");
            }
        }
        CLUSTER_SYNC();
        float* tmp = cur; cur = nxt; nxt = tmp;
    }
}

// ---------------- K3: z = cat @ Wmax^T with max folded over s-pairs ---------
__global__ __launch_bounds__(256, 2)
void ymax_kernel(const float* __restrict__ Wmax) {
    __shared__ float As[2][16][132];
    __shared__ float Bs[2][16][132];
    const int m0 = blockIdx.x * 128;
    const int r0 = blockIdx.y * 128;

    const int t  = threadIdx.x;
    const int tx = t & 15, ty = t >> 4;
    const int lr = t >> 2;
    const int kq = (t & 3) * 4;

    unsigned long long acc2[8][4];
    #pragma unroll
    for (int i = 0; i < 8; ++i)
        #pragma unroll
        for (int j = 0; j < 4; ++j) acc2[i][j] = 0ull;

    {
        const float* Asrc = g_cl;
        float4 a0 = *(const float4*)&Asrc[(size_t)(r0 + lr)      * 512 + kq];
        float4 a1 = *(const float4*)&Asrc[(size_t)(r0 + lr + 64) * 512 + kq];
        float4 b0 = *(const float4*)&Wmax[(size_t)(m0 + lr)      * 1536 + kq];
        float4 b1 = *(const float4*)&Wmax[(size_t)(m0 + lr + 64) * 1536 + kq];
        stor_frag(As[0], kq, lr,      a0);
        stor_frag(As[0], kq, lr + 64, a1);
        stor_frag(Bs[0], kq, lr,      b0);
        stor_frag(Bs[0], kq, lr + 64, b1);
    }
    __syncthreads();

    const int NSTG = 1536 / 16;
    int buf = 0;
    for (int sg = 0; sg < NSTG; ++sg) {
        float4 na0, na1, nb0, nb1;
        if (sg + 1 < NSTG) {
            int kc  = (sg + 1) * 16;
            int sel = kc >> 9;
            const float* Asrc = (sel == 0) ? g_cl : (sel == 1) ? g_emb : g_cr;
            int col = (kc & 511) + kq;
            na0 = *(const float4*)&Asrc[(size_t)(r0 + lr)      * 512 + col];
            na1 = *(const float4*)&Asrc[(size_t)(r0 + lr + 64) * 512 + col];
            nb0 = *(const float4*)&Wmax[(size_t)(m0 + lr)      * 1536 + kc + kq];
            nb1 = *(const float4*)&Wmax[(size_t)(m0 + lr + 64) * 1536 + kc + kq];
        }
        #pragma unroll
        for (int kk = 0; kk < 16; ++kk)
            mm_step(As[buf], Bs[buf], kk, ty, tx, acc2);
        if (sg + 1 < NSTG) {
            stor_frag(As[buf^1], kq, lr,      na0);
            stor_frag(As[buf^1], kq, lr + 64, na1);
            stor_frag(Bs[buf^1], kq, lr,      nb0);
            stor_frag(Bs[buf^1], kq, lr + 64, nb1);
            __syncthreads();
            buf ^= 1;
        }
    }

    const size_t chb = ((size_t)blockIdx.y * BB) * MD;
    #pragma unroll
    for (int i = 0; i < 4; ++i) {
        int b = ty * 4 + i;
        float2 s0p0 = unpk(acc2[i][0]),   s0p1 = unpk(acc2[i][1]);
        float2 s0p2 = unpk(acc2[i][2]),   s0p3 = unpk(acc2[i][3]);
        float2 s1p0 = unpk(acc2[i+4][0]), s1p1 = unpk(acc2[i+4][1]);
        float2 s1p2 = unpk(acc2[i+4][2]), s1p3 = unpk(acc2[i+4][3]);
        float4 o0 = make_float4(fmaxf(s0p0.x,s1p0.x), fmaxf(s0p0.y,s1p0.y),
                                fmaxf(s0p1.x,s1p1.x), fmaxf(s0p1.y,s1p1.y));
        float4 o1 = make_float4(fmaxf(s0p2.x,s1p2.x), fmaxf(s0p2.y,s1p2.y),
                                fmaxf(s0p3.x,s1p3.x), fmaxf(s0p3.y,s1p3.y));
        *(float4*)&g_part[chb + (size_t)b * MD + m0 + tx * 4]      = o0;
        *(float4*)&g_part[chb + (size_t)b * MD + m0 + tx * 4 + 64] = o1;
    }
}

// ---------------- K4: final reduce + tanh + logits + log_softmax ------------
__global__ void head_kernel(const float* __restrict__ bmax,
                            const float* __restrict__ Wdoc,
                            const float* __restrict__ bdoc,
                            float* __restrict__ out) {
    __shared__ float ysh[MD];
    __shared__ float lsh[NC];
    const int b = blockIdx.x;
    const int t = threadIdx.x;
    for (int m = t; m < MD; m += 256) {
        float v = -3.402823466e38f;
        for (int ch = 0; ch < NCH; ++ch)
            v = fmaxf(v, g_part[((size_t)ch * BB + b) * MD + m]);
        ysh[m] = tanhf(v + bmax[m]);
    }
    __syncthreads();
    const int w = t >> 5, lane = t & 31;
    for (int c = w; c < NC; c += 8) {
        float sum = 0.f;
        for (int m = lane; m < MD; m += 32)
            sum += ysh[m] * Wdoc[(size_t)c * MD + m];
        #pragma unroll
        for (int off = 16; off; off >>= 1)
            sum += __shfl_down_sync(0xffffffffu, sum, off);
        if (lane == 0) lsh[c] = sum + bdoc[c];
    }
    __syncthreads();
    if (t == 0) {
        float mx = lsh[0];
        for (int c = 1; c < NC; ++c) mx = fmaxf(mx, lsh[c]);
        float se = 0.f;
        for (int c = 0; c < NC; ++c) se += expf(lsh[c] - mx);
        float lse = logf(se) + mx;
        for (int c = 0; c < NC; ++c) out[b * NC + c] = lsh[c] - lse;
    }
}

// ---------------- launch -----------------------------------------------------
extern "C" void kernel_launch(void* const* d_in, const int* in_sizes, int n_in,
                              void* d_out, int out_size) {
    const int*   inp   = (const int*)  d_in[0];
    const float* table = (const float*)d_in[1];
    const float* cl0   = (const float*)d_in[2];
    const float* cr0   = (const float*)d_in[3];
    const float* Wl    = (const float*)d_in[4];
    const float* bl    = (const float*)d_in[5];
    const float* Wr    = (const float*)d_in[6];
    const float* br    = (const float*)d_in[7];
    const float* Wsl   = (const float*)d_in[8];
    const float* bsl   = (const float*)d_in[9];
    const float* Wsr   = (const float*)d_in[10];
    const float* bsr   = (const float*)d_in[11];
    const float* Wmax  = (const float*)d_in[12];
    const float* bmax  = (const float*)d_in[13];
    const float* Wdoc  = (const float*)d_in[14];
    const float* bdoc  = (const float*)d_in[15];
    float* out = (float*)d_out;

    cudaFuncSetAttribute(scan_kernel,
                         cudaFuncAttributeMaxDynamicSharedMemorySize,
                         SCAN_SMEM_BYTES);

    gather_kernel<<<NROW, 128>>>(inp, table);
    proj_kernel<<<dim3(NROW / 128, 1024 / 128), 256>>>(Wsl, bsl, Wsr, bsr);
    scan_kernel<<<128, 256, SCAN_SMEM_BYTES>>>(Wl, bl, Wr, br, cl0, cr0);
    ymax_kernel<<<dim3(MD / 128, NCH), 256>>>(Wmax);
    head_kernel<<<BB, 256>>>(bmax, Wdoc, bdoc, out);
}